// round 14
// baseline (speedup 1.0000x reference)
#include <cuda_runtime.h>
#include <cuda_bf16.h>

// SoftTimeAttention: out[b,i,:] = sum_j w_ij * h[b,j,:],
//   w_ij = softmax_j( -(T*(t_i - t_j))^2 ), T=4096, tau=1.
// Only ~13/4096 keys per query have fp32-visible weight (cutoff d^2<=40
// drops <2e-14 relative mass; self key weight is exactly 1, sumw >= 1).
//
// R13 post-mortem: attn is ISSUE-bound (issue 69%, occ 38%, DRAM 11%);
// only ~12% of issued instructions were useful FMAs because every lane
// redundantly recomputed the same weights. This version:
//   - lane-parallel weights: lane j computes w[key lo+j][q] for all q
//     (one exp chain per key per WARP, not per lane; 17x fewer MUFU)
//   - shfl-broadcast weights into the FMA loop (71% useful instructions)
//   - QPW=8 sorted queries per warp (2.9 rows gathered per query)
// Sort kernel unchanged (R5-measured 4.2us fused single-CTA counting sort).

#define TT 4096            // sequence length (== softmax scale T)
#define HH 256             // head dim
#define NB 4096            // buckets
#define RADIUS 7           // ceil(sqrt(40)/TT * NB) = 7
#define CUTF 40.0f
#define MAXB 8
#define QPW 8              // sorted queries per warp

__device__ float g_ct  [MAXB * TT];         // t values reordered by bucket
__device__ int   g_cidx[MAXB * TT];         // original indices reordered
__device__ int   g_bstart[MAXB * (NB + 1)]; // bucket start offsets (+ total)

__device__ __forceinline__ int bucket_of(float v) {
    int bi = (int)(v * (float)NB);
    bi = bi < 0 ? 0 : bi;
    bi = bi > NB - 1 ? NB - 1 : bi;
    return bi;
}

// ---------------------------------------------------------------------------
// Kernel 1: fused counting sort by bucket. One 1024-thread CTA per batch.
// (R5-measured: 4.2us. smem atomics, single launch.)
// ---------------------------------------------------------------------------
__global__ void __launch_bounds__(1024, 1)
bucket_kernel(const float* __restrict__ t) {
    __shared__ int hist[NB];   // counts -> exclusive starts
    __shared__ int cur[NB];    // scatter cursors
    __shared__ int wsum[32];

    const int b   = blockIdx.x;
    const int tid = threadIdx.x;             // 1024 threads
    const float4* tb4 = (const float4*)(t + (size_t)b * TT);

    for (int i = tid; i < NB; i += 1024) hist[i] = 0;
    __syncthreads();

    // One float4 per thread covers TT = 4096 exactly.
    const float4 tv = __ldg(tb4 + tid);
    atomicAdd(&hist[bucket_of(tv.x)], 1);
    atomicAdd(&hist[bucket_of(tv.y)], 1);
    atomicAdd(&hist[bucket_of(tv.z)], 1);
    atomicAdd(&hist[bucket_of(tv.w)], 1);
    __syncthreads();

    // Hierarchical exclusive scan over 4096 counts (4 per thread).
    const int base = tid * 4;
    int s0 = hist[base], s1 = hist[base + 1], s2 = hist[base + 2], s3 = hist[base + 3];
    int tot = s0 + s1 + s2 + s3;

    const int lane = tid & 31;
    const int wid  = tid >> 5;
    int v = tot;
    #pragma unroll
    for (int o = 1; o < 32; o <<= 1) {
        int u = __shfl_up_sync(0xFFFFFFFFu, v, o);
        if (lane >= o) v += u;
    }
    if (lane == 31) wsum[wid] = v;
    __syncthreads();
    if (wid == 0) {
        int w = wsum[lane];
        #pragma unroll
        for (int o = 1; o < 32; o <<= 1) {
            int u = __shfl_up_sync(0xFFFFFFFFu, w, o);
            if (lane >= o) w += u;
        }
        wsum[lane] = w;   // inclusive scan of per-warp totals
    }
    __syncthreads();

    int excl = v - tot + (wid > 0 ? wsum[wid - 1] : 0);
    const int st0 = excl, st1 = st0 + s0, st2 = st1 + s1, st3 = st2 + s2;

    cur[base] = st0; cur[base + 1] = st1; cur[base + 2] = st2; cur[base + 3] = st3;

    int* gb = g_bstart + b * (NB + 1);
    gb[base] = st0; gb[base + 1] = st1; gb[base + 2] = st2; gb[base + 3] = st3;
    if (tid == 0) gb[NB] = TT;
    __syncthreads();

    // Scatter t and original index by bucket (reuse the registered float4).
    float* ct = g_ct   + b * TT;
    int*   ci = g_cidx + b * TT;
    {
        const int i0 = tid * 4;
        int p;
        p = atomicAdd(&cur[bucket_of(tv.x)], 1); ct[p] = tv.x; ci[p] = i0 + 0;
        p = atomicAdd(&cur[bucket_of(tv.y)], 1); ct[p] = tv.y; ci[p] = i0 + 1;
        p = atomicAdd(&cur[bucket_of(tv.z)], 1); ct[p] = tv.z; ci[p] = i0 + 2;
        p = atomicAdd(&cur[bucket_of(tv.w)], 1); ct[p] = tv.w; ci[p] = i0 + 3;
    }
}

// ---------------------------------------------------------------------------
// Kernel 2: one warp per (QPW=8 sorted queries, half of H). 8 warps / CTA.
// Warp tasks per batch: (TT/QPW) * 2 = 1024.
// Weights computed lane-parallel per 32-key chunk, broadcast via shfl.
// ---------------------------------------------------------------------------
__global__ void __launch_bounds__(256)
attn_kernel(const float* __restrict__ h, float* __restrict__ out) {
    const int gw   = (blockIdx.x * 256 + threadIdx.x) >> 5; // global warp id
    const int lane = threadIdx.x & 31;
    const int b    = gw >> 10;               // / 1024 tasks per batch
    const int task = gw & 1023;
    const int hsel = task & 1;               // which 128-col half
    const int p0   = (task >> 1) * QPW;      // first sorted position

    const float* ct = g_ct   + ((size_t)b << 12);
    const int*   ci = g_cidx + ((size_t)b << 12);

    float tq[QPW];
    #pragma unroll
    for (int q = 0; q < QPW; ++q)
        tq[q] = __ldg(ct + p0 + q);          // sorted ascending

    // Union key window across the QPW queries.
    const int* gb = g_bstart + b * (NB + 1);
    const int lob = bucket_of(tq[0]) - RADIUS;
    const int hib = bucket_of(tq[QPW - 1]) + RADIUS + 1;
    const int lo = __ldg(gb + (lob < 0 ? 0 : lob));
    const int hi = __ldg(gb + (hib > NB ? NB : hib));

    // Base of this warp's half-row: cols [hsel*128, hsel*128+128).
    const float* hb = h + (((size_t)b << 12)) * HH + (hsel << 7);

    float4 acc[QPW];
    float  sw[QPW];                          // per-lane partial sums of w
    #pragma unroll
    for (int q = 0; q < QPW; ++q) {
        acc[q] = make_float4(0.f, 0.f, 0.f, 0.f);
        sw[q]  = 0.f;
    }

    for (int base = lo; base < hi; base += 32) {
        // Lane j owns key (base + j): one weight chain per KEY, not per lane.
        const int j = base + lane;
        float tk  = 1e9f;                    // invalid lanes -> d2 huge -> w=0
        int   kidx = 0;
        if (j < hi) { tk = __ldg(ct + j); kidx = __ldg(ci + j); }

        float wv[QPW];
        #pragma unroll
        for (int q = 0; q < QPW; ++q) {
            const float d  = (float)TT * (tq[q] - tk);
            float d2 = d * d;
            d2 = d2 > CUTF ? 999.0f : d2;    // exp(-999) == +0.0f guaranteed
            wv[q] = __expf(-d2);
            sw[q] += wv[q];
        }

        const int nk = min(hi - base, 32);
        #pragma unroll 2
        for (int jj = 0; jj < nk; ++jj) {
            const int idx = __shfl_sync(0xFFFFFFFFu, kidx, jj);
            const float4 v = __ldg((const float4*)(hb + (size_t)idx * HH) + lane);
            #pragma unroll
            for (int q = 0; q < QPW; ++q) {
                const float w = __shfl_sync(0xFFFFFFFFu, wv[q], jj);
                acc[q].x = fmaf(w, v.x, acc[q].x);
                acc[q].y = fmaf(w, v.y, acc[q].y);
                acc[q].z = fmaf(w, v.z, acc[q].z);
                acc[q].w = fmaf(w, v.w, acc[q].w);
            }
        }
    }

    // Reduce per-lane weight sums across the warp (each key counted once).
    #pragma unroll
    for (int q = 0; q < QPW; ++q) {
        #pragma unroll
        for (int o = 16; o > 0; o >>= 1)
            sw[q] += __shfl_xor_sync(0xFFFFFFFFu, sw[q], o);
    }

    #pragma unroll
    for (int q = 0; q < QPW; ++q) {
        const float inv = 1.0f / sw[q];      // sumw >= 1 (self key weight == 1)
        const int iq = __ldg(ci + p0 + q);   // original query index
        float4 o4 = make_float4(acc[q].x * inv, acc[q].y * inv,
                                acc[q].z * inv, acc[q].w * inv);
        float4* orow = (float4*)(out + ((size_t)(((size_t)b << 12) + iq)) * HH
                                 + (hsel << 7));
        orow[lane] = o4;
    }
}

// ---------------------------------------------------------------------------
extern "C" void kernel_launch(void* const* d_in, const int* in_sizes, int n_in,
                              void* d_out, int out_size) {
    const float* h = (const float*)d_in[0];   // h_seq: (B, T, H) fp32
    const float* t = (const float*)d_in[1];   // t:     (B, T, 1) fp32
    float* out = (float*)d_out;               // (B, T, H) fp32

    int B = in_sizes[1] / TT;
    if (B < 1) B = 1;
    if (B > MAXB) B = MAXB;

    bucket_kernel<<<B, 1024>>>(t);
    // B * 1024 warp tasks, 8 warps per CTA.
    attn_kernel<<<B * 1024 / 8, 256>>>(h, out);
}

// round 16
// speedup vs baseline: 1.4033x; 1.4033x over previous
#include <cuda_runtime.h>
#include <cuda_bf16.h>

// SoftTimeAttention: out[b,i,:] = sum_j w_ij * h[b,j,:],
//   w_ij = softmax_j( -(T*(t_i - t_j))^2 ), T=4096, tau=1.
// Only ~13/4096 keys per query have fp32-visible weight; self key weight is
// exactly 1 so sumw >= 1 and no max-subtraction is needed.
//
// R14 post-mortem: shfl-broadcast weights REGRESSED (28.1us, issue 34%) —
// the shfl'd index serialized every gather load. Reverted to R13 structure
// (best attn: 19.7us @ issue 69%) and shaved the issue bottleneck instead:
//   - (t, idx) packed in one float2 -> 1 LDG.64/key instead of 2 LDG.32
//   - softmax scale folded into times: w = ex2(-(aq-bs)^2), 3 instr/q chain
//   - no clamp needed (window-bounded d^2 -> ex2 underflows harmlessly)
//   - __launch_bounds__(256,5): 51-reg cap -> 5 CTAs/SM (was 4 @ 55 regs)
// Sort kernel: R5-measured fused single-CTA counting sort (4.2us).

#define TT 4096            // sequence length (== softmax scale T)
#define HH 256             // head dim
#define NB 4096            // buckets
#define RADIUS 7           // ceil(sqrt(40)/TT * NB) = 7
#define MAXB 8
#define QPW 4              // sorted queries per warp
#define SCL 4919.7974f     // TT * sqrt(log2(e)); w = 2^(-(SCL*dt)^2) = e^(-(TT*dt)^2)

__device__ float2 g_ctci[MAXB * TT];        // (t value, idx-as-float) by bucket
__device__ int    g_bstart[MAXB * (NB + 1)];// bucket start offsets (+ total)

__device__ __forceinline__ int bucket_of(float v) {
    int bi = (int)(v * (float)NB);
    bi = bi < 0 ? 0 : bi;
    bi = bi > NB - 1 ? NB - 1 : bi;
    return bi;
}

// ---------------------------------------------------------------------------
// Kernel 1: fused counting sort by bucket. One 1024-thread CTA per batch.
// ---------------------------------------------------------------------------
__global__ void __launch_bounds__(1024, 1)
bucket_kernel(const float* __restrict__ t) {
    __shared__ int hist[NB];   // counts -> exclusive starts
    __shared__ int cur[NB];    // scatter cursors
    __shared__ int wsum[32];

    const int b   = blockIdx.x;
    const int tid = threadIdx.x;             // 1024 threads
    const float4* tb4 = (const float4*)(t + (size_t)b * TT);

    for (int i = tid; i < NB; i += 1024) hist[i] = 0;
    __syncthreads();

    // One float4 per thread covers TT = 4096 exactly.
    const float4 tv = __ldg(tb4 + tid);
    atomicAdd(&hist[bucket_of(tv.x)], 1);
    atomicAdd(&hist[bucket_of(tv.y)], 1);
    atomicAdd(&hist[bucket_of(tv.z)], 1);
    atomicAdd(&hist[bucket_of(tv.w)], 1);
    __syncthreads();

    // Hierarchical exclusive scan over 4096 counts (4 per thread).
    const int base = tid * 4;
    int s0 = hist[base], s1 = hist[base + 1], s2 = hist[base + 2], s3 = hist[base + 3];
    int tot = s0 + s1 + s2 + s3;

    const int lane = tid & 31;
    const int wid  = tid >> 5;
    int v = tot;
    #pragma unroll
    for (int o = 1; o < 32; o <<= 1) {
        int u = __shfl_up_sync(0xFFFFFFFFu, v, o);
        if (lane >= o) v += u;
    }
    if (lane == 31) wsum[wid] = v;
    __syncthreads();
    if (wid == 0) {
        int w = wsum[lane];
        #pragma unroll
        for (int o = 1; o < 32; o <<= 1) {
            int u = __shfl_up_sync(0xFFFFFFFFu, w, o);
            if (lane >= o) w += u;
        }
        wsum[lane] = w;   // inclusive scan of per-warp totals
    }
    __syncthreads();

    int excl = v - tot + (wid > 0 ? wsum[wid - 1] : 0);
    const int st0 = excl, st1 = st0 + s0, st2 = st1 + s1, st3 = st2 + s2;

    cur[base] = st0; cur[base + 1] = st1; cur[base + 2] = st2; cur[base + 3] = st3;

    int* gb = g_bstart + b * (NB + 1);
    gb[base] = st0; gb[base + 1] = st1; gb[base + 2] = st2; gb[base + 3] = st3;
    if (tid == 0) gb[NB] = TT;
    __syncthreads();

    // Scatter (t, idx) pairs by bucket (one STG.64 per element).
    float2* cc = g_ctci + b * TT;
    {
        const int i0 = tid * 4;
        int p;
        p = atomicAdd(&cur[bucket_of(tv.x)], 1); cc[p] = make_float2(tv.x, __int_as_float(i0 + 0));
        p = atomicAdd(&cur[bucket_of(tv.y)], 1); cc[p] = make_float2(tv.y, __int_as_float(i0 + 1));
        p = atomicAdd(&cur[bucket_of(tv.z)], 1); cc[p] = make_float2(tv.z, __int_as_float(i0 + 2));
        p = atomicAdd(&cur[bucket_of(tv.w)], 1); cc[p] = make_float2(tv.w, __int_as_float(i0 + 3));
    }
}

// ---------------------------------------------------------------------------
// Kernel 2: one warp per (QPW sorted queries, half of H). 8 warps / CTA.
// Warp tasks per batch: (TT/QPW) * 2 = 2048. hsel is the LOW bit so the two
// halves of the same query group sit in the same CTA (shared L1 rows).
// ---------------------------------------------------------------------------
__global__ void __launch_bounds__(256, 5)
attn_kernel(const float* __restrict__ h, float* __restrict__ out) {
    const int gw   = (blockIdx.x * 256 + threadIdx.x) >> 5; // global warp id
    const int lane = threadIdx.x & 31;
    const int b    = gw >> 11;               // / 2048 tasks per batch
    const int task = gw & 2047;
    const int hsel = task & 1;               // which 128-col half
    const int p0   = (task >> 1) * QPW;      // first sorted position

    const float2* ctci = g_ctci + ((size_t)b << 12);

    float aq[QPW];                           // pre-scaled query times
    float tfirst, tlast;
    #pragma unroll
    for (int q = 0; q < QPW; ++q) {
        const float2 pq = __ldg(ctci + p0 + q);
        if (q == 0)       tfirst = pq.x;
        if (q == QPW - 1) tlast  = pq.x;
        aq[q] = SCL * pq.x;
    }

    // Union key window across the QPW queries.
    const int* gb = g_bstart + b * (NB + 1);
    const int lob = bucket_of(tfirst) - RADIUS;
    const int hib = bucket_of(tlast) + RADIUS + 1;
    const int lo = __ldg(gb + (lob < 0 ? 0 : lob));
    const int hi = __ldg(gb + (hib > NB ? NB : hib));

    // Base of this warp's half-row: cols [hsel*128, hsel*128+128).
    const float* hb = h + (((size_t)b << 12)) * HH + (hsel << 7);

    float4 acc[QPW];
    float  sw[QPW];
    #pragma unroll
    for (int q = 0; q < QPW; ++q) {
        acc[q] = make_float4(0.f, 0.f, 0.f, 0.f);
        sw[q]  = 0.f;
    }

    #pragma unroll 2
    for (int j = lo; j < hi; ++j) {
        const float2 kp = __ldg(ctci + j);   // (tk, idx) in one LDG.64
        const float bs  = SCL * kp.x;
        const int   idx = __float_as_int(kp.y);
        const float4 v  = __ldg((const float4*)(hb + ((size_t)idx << 8)) + lane);

        #pragma unroll
        for (int q = 0; q < QPW; ++q) {
            const float d = aq[q] - bs;
            const float x = d * -d;          // -(SCL*dt)^2 = -(TT*dt)^2*log2(e)
            float w;
            asm("ex2.approx.ftz.f32 %0, %1;" : "=f"(w) : "f"(x));
            sw[q] += w;
            acc[q].x = fmaf(w, v.x, acc[q].x);
            acc[q].y = fmaf(w, v.y, acc[q].y);
            acc[q].z = fmaf(w, v.z, acc[q].z);
            acc[q].w = fmaf(w, v.w, acc[q].w);
        }
    }

    #pragma unroll
    for (int q = 0; q < QPW; ++q) {
        const float inv = 1.0f / sw[q];      // sumw >= 1 (self key weight == 1)
        const int iq = __float_as_int(__ldg(ctci + p0 + q).y);  // L1-hot reload
        float4 o4 = make_float4(acc[q].x * inv, acc[q].y * inv,
                                acc[q].z * inv, acc[q].w * inv);
        float4* orow = (float4*)(out + ((size_t)(((size_t)b << 12) + iq)) * HH
                                 + (hsel << 7));
        orow[lane] = o4;
    }
}

// ---------------------------------------------------------------------------
extern "C" void kernel_launch(void* const* d_in, const int* in_sizes, int n_in,
                              void* d_out, int out_size) {
    const float* h = (const float*)d_in[0];   // h_seq: (B, T, H) fp32
    const float* t = (const float*)d_in[1];   // t:     (B, T, 1) fp32
    float* out = (float*)d_out;               // (B, T, H) fp32

    int B = in_sizes[1] / TT;
    if (B < 1) B = 1;
    if (B > MAXB) B = MAXB;

    bucket_kernel<<<B, 1024>>>(t);
    // B * 2048 warp tasks, 8 warps per CTA.
    attn_kernel<<<B * 2048 / 8, 256>>>(h, out);
}